// round 1
// baseline (speedup 1.0000x reference)
#include <cuda_runtime.h>
#include <cuda_bf16.h>
#include <cstdint>

#define BB 4
#define NN 8192
#define SS 2048
#define KK 16
#define DD 64
#define MTOT (BB*SS*KK)   // 131072
#define NEL_INV (1.0f/131072.0f)

// ---------------- scratch (__device__ globals; no runtime alloc) ----------------
__device__ float4 g_pts4[BB*NN];          // x,y,z,|p|^2
__device__ int    g_fps [BB*SS];
__device__ int    g_knn [BB*SS*KK];
__device__ float  g_y0  [64 * MTOT];
__device__ float  g_y1  [64 * MTOT];
__device__ float  g_y2  [128 * MTOT];
__device__ float  g_raw [512];            // sum/sumsq per layer
__device__ float  g_st  [512];            // folded scale/shift per layer

__device__ __forceinline__ float f_inf() { return __int_as_float(0x7f800000); }

// ---------------- zero stats ----------------
__global__ void zero_kernel() { g_raw[threadIdx.x] = 0.0f; }

// ---------------- pack points + norms ----------------
__global__ void prep_kernel(const float* __restrict__ xyz) {
    int t = blockIdx.x * 256 + threadIdx.x;      // 0..32767
    int b = t >> 13, n = t & (NN - 1);
    const float* X = xyz + (size_t)b * 3 * NN;
    float x = X[n], y = X[NN + n], z = X[2 * NN + n];
    float nrm = __fadd_rn(__fadd_rn(__fmul_rn(x, x), __fmul_rn(y, y)), __fmul_rn(z, z));
    g_pts4[t] = make_float4(x, y, z, nrm);
}

// ---------------- FPS: one block per batch, sequential ----------------
__global__ __launch_bounds__(1024, 1) void fps_kernel(const float* __restrict__ xyz) {
    int b = blockIdx.x;
    const float* X = xyz + (size_t)b * 3 * NN;
    int tid = threadIdx.x;

    float px[8], py[8], pz[8], dd[8];
#pragma unroll
    for (int j = 0; j < 8; j++) {
        int p = tid + j * 1024;
        px[j] = X[p]; py[j] = X[NN + p]; pz[j] = X[2 * NN + p];
        dd[j] = 1e10f;
    }
    __shared__ float scx, scy, scz;
    __shared__ int   swi;
    __shared__ float rv[32];
    __shared__ int   ri[32];

    if (tid == 0) { g_fps[b * SS] = 0; scx = X[0]; scy = X[NN]; scz = X[2 * NN]; }
    __syncthreads();

    for (int it = 1; it < SS; it++) {
        float cx = scx, cy = scy, cz = scz;
        float bv = -1.0f; int bi = 0x7fffffff;
#pragma unroll
        for (int j = 0; j < 8; j++) {
            float dx = __fsub_rn(px[j], cx);
            float dy = __fsub_rn(py[j], cy);
            float dz = __fsub_rn(pz[j], cz);
            float d  = __fadd_rn(__fadd_rn(__fmul_rn(dx, dx), __fmul_rn(dy, dy)), __fmul_rn(dz, dz));
            float nd = fminf(dd[j], d);
            dd[j] = nd;
            if (nd > bv) { bv = nd; bi = tid + j * 1024; }  // ascending idx -> first-max kept
        }
        // warp argmax (lowest index on ties)
#pragma unroll
        for (int off = 16; off; off >>= 1) {
            float ov = __shfl_down_sync(0xffffffffu, bv, off);
            int   oi = __shfl_down_sync(0xffffffffu, bi, off);
            if (ov > bv || (ov == bv && oi < bi)) { bv = ov; bi = oi; }
        }
        if ((tid & 31) == 0) { rv[tid >> 5] = bv; ri[tid >> 5] = bi; }
        __syncthreads();
        if (tid < 32) {
            bv = rv[tid]; bi = ri[tid];
#pragma unroll
            for (int off = 16; off; off >>= 1) {
                float ov = __shfl_down_sync(0xffffffffu, bv, off);
                int   oi = __shfl_down_sync(0xffffffffu, bi, off);
                if (ov > bv || (ov == bv && oi < bi)) { bv = ov; bi = oi; }
            }
            if (tid == 0) { swi = bi; g_fps[b * SS + it] = bi; }
        }
        __syncthreads();
        int wi = swi;
#pragma unroll
        for (int j = 0; j < 8; j++) {
            if (wi == tid + j * 1024) { scx = px[j]; scy = py[j]; scz = pz[j]; }
        }
        __syncthreads();
    }
}

// ---------------- kNN: one warp per query, smem-tiled candidates ----------------
__global__ __launch_bounds__(256) void knn_kernel() {
    __shared__ float4 sp[1024];
    int b = blockIdx.x >> 8;                 // 256 blocks per batch
    int s = ((blockIdx.x & 255) << 3) + (threadIdx.x >> 5);
    int lane = threadIdx.x & 31;

    int qi = g_fps[b * SS + s];
    float4 q = g_pts4[b * NN + qi];

    float bd[16]; int bn[16];
#pragma unroll
    for (int j = 0; j < 16; j++) { bd[j] = f_inf(); bn[j] = 0x7fffffff; }

    for (int ch = 0; ch < 8; ch++) {
        __syncthreads();
#pragma unroll
        for (int i = 0; i < 4; i++)
            sp[threadIdx.x + i * 256] = g_pts4[b * NN + ch * 1024 + threadIdx.x + i * 256];
        __syncthreads();
#pragma unroll 4
        for (int i = 0; i < 32; i++) {
            int ci = lane + i * 32;
            float4 p = sp[ci];
            float dot = q.x * p.x + q.y * p.y + q.z * p.z;
            float d = __fadd_rn(__fadd_rn(__fmul_rn(-2.0f, dot), q.w), p.w);
            int gi = ch * 1024 + ci;
            bool worse15 = (d > bd[15]) || (d == bd[15] && gi > bn[15]);
            if (!worse15) {
                float cd = d; int cn = gi;
#pragma unroll
                for (int j = 0; j < 16; j++) {
                    bool sw = (cd < bd[j]) || (cd == bd[j] && cn < bn[j]);
                    float td = bd[j]; int tn = bn[j];
                    if (sw) { bd[j] = cd; bn[j] = cn; cd = td; cn = tn; }
                }
            }
        }
    }
    // merge 32 sorted-16 lists -> global 16 smallest
    int myOut = 0;
#pragma unroll
    for (int r = 0; r < 16; r++) {
        unsigned fb = __float_as_uint(bd[0]);
        fb ^= (((unsigned)((int)fb >> 31)) | 0x80000000u);
        unsigned long long key = ((unsigned long long)fb << 32) | (unsigned)bn[0];
        unsigned long long mykey = key;
#pragma unroll
        for (int off = 16; off; off >>= 1) {
            unsigned long long o = __shfl_xor_sync(0xffffffffu, key, off);
            key = (o < key) ? o : key;
        }
        if (lane == r) myOut = (int)(unsigned)(key & 0xffffffffULL);
        if (mykey == key) {
#pragma unroll
            for (int j = 0; j < 15; j++) { bd[j] = bd[j + 1]; bn[j] = bn[j + 1]; }
            bd[15] = f_inf(); bn[15] = 0x7fffffff;
        }
    }
    if (lane < 16) g_knn[(b * SS + s) * KK + lane] = myOut;
}

// ---------------- conv0: gather(67ch) + GEMM 67->64 + stats ----------------
__global__ __launch_bounds__(128) void conv0_kernel(const float* __restrict__ xyz,
                                                    const float* __restrict__ pts,
                                                    const float* __restrict__ W) {
    extern __shared__ float sm[];
    float* Xs = sm;               // [67][128]
    float* Wt = sm + 67 * 128;    // [67][64] (transposed)
    int tid = threadIdx.x;
    int m0 = blockIdx.x * 128;

    for (int i = tid; i < 67 * 64; i += 128) {
        int o = i / 67, c = i - o * 67;
        Wt[c * 64 + o] = W[i];
    }
    {
        int m = m0 + tid;
        int b = m >> 15; int rem = m & 32767; int s = rem >> 4; int k = rem & 15;
        int ni = g_knn[(((b << 11) + s) << 4) + k];
        int qi = g_fps[(b << 11) + s];
        const float* xb = xyz + (size_t)b * 3 * NN;
        Xs[0 * 128 + tid] = xb[ni] - xb[qi];
        Xs[1 * 128 + tid] = xb[NN + ni] - xb[NN + qi];
        Xs[2 * 128 + tid] = xb[2 * NN + ni] - xb[2 * NN + qi];
        const float* pb = pts + (size_t)b * DD * NN;
#pragma unroll
        for (int c = 0; c < 64; c++) Xs[(c + 3) * 128 + tid] = pb[c * NN + ni];
    }
    __syncthreads();

    int og = tid >> 5, mt = tid & 31;
    float acc[16][4];
#pragma unroll
    for (int o = 0; o < 16; o++)
#pragma unroll
        for (int j = 0; j < 4; j++) acc[o][j] = 0.0f;

    for (int c = 0; c < 67; c++) {
        float4 xv = *(const float4*)(Xs + c * 128 + mt * 4);
        float w[16];
        *(float4*)&w[0]  = *(const float4*)(Wt + c * 64 + og * 16);
        *(float4*)&w[4]  = *(const float4*)(Wt + c * 64 + og * 16 + 4);
        *(float4*)&w[8]  = *(const float4*)(Wt + c * 64 + og * 16 + 8);
        *(float4*)&w[12] = *(const float4*)(Wt + c * 64 + og * 16 + 12);
#pragma unroll
        for (int o = 0; o < 16; o++) {
            acc[o][0] += w[o] * xv.x; acc[o][1] += w[o] * xv.y;
            acc[o][2] += w[o] * xv.z; acc[o][3] += w[o] * xv.w;
        }
    }
    float s1[16], s2[16];
#pragma unroll
    for (int o = 0; o < 16; o++) {
        float4 v = make_float4(acc[o][0], acc[o][1], acc[o][2], acc[o][3]);
        *(float4*)(g_y0 + (size_t)(og * 16 + o) * MTOT + m0 + mt * 4) = v;
        s1[o] = v.x + v.y + v.z + v.w;
        s2[o] = v.x * v.x + v.y * v.y + v.z * v.z + v.w * v.w;
    }
#pragma unroll
    for (int off = 16; off; off >>= 1) {
#pragma unroll
        for (int o = 0; o < 16; o++) {
            s1[o] += __shfl_down_sync(0xffffffffu, s1[o], off);
            s2[o] += __shfl_down_sync(0xffffffffu, s2[o], off);
        }
    }
    if (mt == 0) {
#pragma unroll
        for (int o = 0; o < 16; o++) {
            atomicAdd(&g_raw[og * 16 + o], s1[o]);
            atomicAdd(&g_raw[64 + og * 16 + o], s2[o]);
        }
    }
}

// ---------------- mid conv: apply prev BN+leaky, GEMM, stats ----------------
template <int CIN, int COUT>
__global__ __launch_bounds__((COUT / 16) * 32) void convmid_kernel(
    const float* __restrict__ Yin, float* __restrict__ Yout,
    const float* __restrict__ W, int stIn, int rawOut) {
    constexpr int TPB = (COUT / 16) * 32;
    extern __shared__ float sm[];
    float* Xs = sm;                 // [CIN][128]
    float* Wt = sm + CIN * 128;     // [CIN][COUT]
    int tid = threadIdx.x;
    int m0 = blockIdx.x * 128;

    for (int i = tid; i < CIN * COUT; i += TPB) {
        int o = i / CIN, c = i - o * CIN;
        Wt[c * COUT + o] = W[i];
    }
    for (int i = tid; i < CIN * 128; i += TPB) {
        int c = i >> 7, ml = i & 127;
        float v = Yin[(size_t)c * MTOT + m0 + ml];
        v = v * g_st[stIn + c] + g_st[stIn + CIN + c];
        v = (v > 0.0f) ? v : 0.1f * v;
        Xs[i] = v;
    }
    __syncthreads();

    int og = tid >> 5, mt = tid & 31;
    float acc[16][4];
#pragma unroll
    for (int o = 0; o < 16; o++)
#pragma unroll
        for (int j = 0; j < 4; j++) acc[o][j] = 0.0f;

    for (int c = 0; c < CIN; c++) {
        float4 xv = *(const float4*)(Xs + c * 128 + mt * 4);
        float w[16];
        *(float4*)&w[0]  = *(const float4*)(Wt + c * COUT + og * 16);
        *(float4*)&w[4]  = *(const float4*)(Wt + c * COUT + og * 16 + 4);
        *(float4*)&w[8]  = *(const float4*)(Wt + c * COUT + og * 16 + 8);
        *(float4*)&w[12] = *(const float4*)(Wt + c * COUT + og * 16 + 12);
#pragma unroll
        for (int o = 0; o < 16; o++) {
            acc[o][0] += w[o] * xv.x; acc[o][1] += w[o] * xv.y;
            acc[o][2] += w[o] * xv.z; acc[o][3] += w[o] * xv.w;
        }
    }
    float s1[16], s2[16];
#pragma unroll
    for (int o = 0; o < 16; o++) {
        float4 v = make_float4(acc[o][0], acc[o][1], acc[o][2], acc[o][3]);
        *(float4*)(Yout + (size_t)(og * 16 + o) * MTOT + m0 + mt * 4) = v;
        s1[o] = v.x + v.y + v.z + v.w;
        s2[o] = v.x * v.x + v.y * v.y + v.z * v.z + v.w * v.w;
    }
#pragma unroll
    for (int off = 16; off; off >>= 1) {
#pragma unroll
        for (int o = 0; o < 16; o++) {
            s1[o] += __shfl_down_sync(0xffffffffu, s1[o], off);
            s2[o] += __shfl_down_sync(0xffffffffu, s2[o], off);
        }
    }
    if (mt == 0) {
#pragma unroll
        for (int o = 0; o < 16; o++) {
            atomicAdd(&g_raw[rawOut + og * 16 + o], s1[o]);
            atomicAdd(&g_raw[rawOut + COUT + og * 16 + o], s2[o]);
        }
    }
}

// ---------------- finalize BN stats -> folded scale/shift ----------------
__global__ void finalize_kernel(int rawOff, int stOff, int C,
                                const float* __restrict__ gamma,
                                const float* __restrict__ beta) {
    int c = threadIdx.x;
    if (c < C) {
        float su = g_raw[rawOff + c], sq = g_raw[rawOff + C + c];
        float mean = su * NEL_INV;
        float var = sq * NEL_INV - mean * mean;
        float s = gamma[c] * rsqrtf(var + 1e-5f);
        g_st[stOff + c] = s;
        g_st[stOff + C + c] = beta[c] - mean * s;
    }
}

// ---------------- final: bn2 + leaky + max over K -> feat ----------------
__global__ __launch_bounds__(256) void feat_kernel(float* __restrict__ out) {
    int t = blockIdx.x * 256 + threadIdx.x;   // 1,048,576 = B*128*S
    int s = t & 2047;
    int o = (t >> 11) & 127;
    int b = t >> 18;
    float sc = g_st[256 + o], tb = g_st[384 + o];
    const float4* yp = (const float4*)(g_y2 + (size_t)o * MTOT + (size_t)(((b << 11) + s) << 4));
    float mx = -f_inf();
#pragma unroll
    for (int i = 0; i < 4; i++) {
        float4 v = yp[i];
        float a;
        a = v.x * sc + tb; a = (a > 0.0f) ? a : 0.1f * a; mx = fmaxf(mx, a);
        a = v.y * sc + tb; a = (a > 0.0f) ? a : 0.1f * a; mx = fmaxf(mx, a);
        a = v.z * sc + tb; a = (a > 0.0f) ? a : 0.1f * a; mx = fmaxf(mx, a);
        a = v.w * sc + tb; a = (a > 0.0f) ? a : 0.1f * a; mx = fmaxf(mx, a);
    }
    out[24576 + (size_t)(((b << 7) | o) << 11) + s] = mx;
}

// ---------------- aux: new_xyz + fps_idx ----------------
__global__ __launch_bounds__(256) void aux_kernel(const float* __restrict__ xyz,
                                                  float* __restrict__ out) {
    int t = blockIdx.x * 256 + threadIdx.x;   // 32768 = B*4*S
    int b = t >> 13;
    int r = t & 8191;
    int c = r >> 11;       // 0..3
    int s = r & 2047;
    int fi = g_fps[(b << 11) + s];
    if (c < 3) out[(size_t)(((b * 3 + c) << 11)) + s] = xyz[(size_t)(b * 3 + c) * NN + fi];
    else       out[24576 + 1048576 + (size_t)(b << 11) + s] = (float)fi;
}

// ---------------- launch ----------------
extern "C" void kernel_launch(void* const* d_in, const int* in_sizes, int n_in,
                              void* d_out, int out_size) {
    const float* xyz = (const float*)d_in[0];
    const float* pts = (const float*)d_in[1];
    const float* w0  = (const float*)d_in[2];
    const float* w1  = (const float*)d_in[3];
    const float* w2  = (const float*)d_in[4];
    const float* bn0g = (const float*)d_in[5];
    const float* bn0b = (const float*)d_in[6];
    const float* bn1g = (const float*)d_in[7];
    const float* bn1b = (const float*)d_in[8];
    const float* bn2g = (const float*)d_in[9];
    const float* bn2b = (const float*)d_in[10];
    float* out = (float*)d_out;

    float *y0p, *y1p, *y2p;
    cudaGetSymbolAddress((void**)&y0p, g_y0);
    cudaGetSymbolAddress((void**)&y1p, g_y1);
    cudaGetSymbolAddress((void**)&y2p, g_y2);

    const int SM0 = (67 * 128 + 67 * 64) * 4;     // 51456
    const int SM1 = (64 * 128 + 64 * 64) * 4;     // 49152
    const int SM2 = (64 * 128 + 64 * 128) * 4;    // 65536
    cudaFuncSetAttribute(conv0_kernel, cudaFuncAttributeMaxDynamicSharedMemorySize, SM0);
    cudaFuncSetAttribute(convmid_kernel<64, 64>, cudaFuncAttributeMaxDynamicSharedMemorySize, SM1);
    cudaFuncSetAttribute(convmid_kernel<64, 128>, cudaFuncAttributeMaxDynamicSharedMemorySize, SM2);

    zero_kernel<<<1, 512>>>();
    prep_kernel<<<(BB * NN) / 256, 256>>>(xyz);
    fps_kernel<<<BB, 1024>>>(xyz);
    knn_kernel<<<1024, 256>>>();
    conv0_kernel<<<MTOT / 128, 128, SM0>>>(xyz, pts, w0);
    finalize_kernel<<<1, 64>>>(0, 0, 64, bn0g, bn0b);
    convmid_kernel<64, 64><<<MTOT / 128, 128, SM1>>>(y0p, y1p, w1, 0, 128);
    finalize_kernel<<<1, 64>>>(128, 128, 64, bn1g, bn1b);
    convmid_kernel<64, 128><<<MTOT / 128, 256, SM2>>>(y1p, y2p, w2, 128, 256);
    finalize_kernel<<<1, 128>>>(256, 256, 128, bn2g, bn2b);
    feat_kernel<<<(BB * 128 * SS) / 256, 256>>>(out);
    aux_kernel<<<(BB * 4 * SS) / 256, 256>>>(xyz, out);
}

// round 3
// speedup vs baseline: 2.2910x; 2.2910x over previous
#include <cuda_runtime.h>
#include <cuda_bf16.h>
#include <cstdint>

#define BB 4
#define NN 8192
#define SS 2048
#define KK 16
#define DD 64
#define MTOT (BB*SS*KK)   // 131072
#define NEL_INV (1.0f/131072.0f)

typedef unsigned long long u64;

// ---------------- scratch (__device__ globals; no runtime alloc) ----------------
__device__ float4 g_pts4[BB*NN];          // x,y,z,|p|^2
__device__ int    g_fps [BB*SS];
__device__ int    g_knn [BB*SS*KK];
__device__ float  g_y0  [64 * MTOT];
__device__ float  g_y1  [64 * MTOT];
__device__ float  g_y2  [128 * MTOT];
__device__ float  g_raw [512];            // sum/sumsq per layer
__device__ float  g_st  [512];            // folded scale/shift per layer

__device__ __forceinline__ float f_inf() { return __int_as_float(0x7f800000); }

// packed f32x2 helpers (element-wise .rn — bit-identical to scalar __fmul_rn/__fadd_rn)
__device__ __forceinline__ u64 pk2(float lo, float hi) {
    u64 r; asm("mov.b64 %0,{%1,%2};" : "=l"(r) : "f"(lo), "f"(hi)); return r;
}
__device__ __forceinline__ void upk2(u64 v, float& lo, float& hi) {
    asm("mov.b64 {%0,%1},%2;" : "=f"(lo), "=f"(hi) : "l"(v));
}
__device__ __forceinline__ u64 add2(u64 a, u64 b) {
    u64 r; asm("add.rn.f32x2 %0,%1,%2;" : "=l"(r) : "l"(a), "l"(b)); return r;
}
__device__ __forceinline__ u64 mul2(u64 a, u64 b) {
    u64 r; asm("mul.rn.f32x2 %0,%1,%2;" : "=l"(r) : "l"(a), "l"(b)); return r;
}

// ---------------- zero stats ----------------
__global__ void zero_kernel() { g_raw[threadIdx.x] = 0.0f; }

// ---------------- pack points + norms ----------------
__global__ void prep_kernel(const float* __restrict__ xyz) {
    int t = blockIdx.x * 256 + threadIdx.x;      // 0..32767
    int b = t >> 13, n = t & (NN - 1);
    const float* X = xyz + (size_t)b * 3 * NN;
    float x = X[n], y = X[NN + n], z = X[2 * NN + n];
    float nrm = __fadd_rn(__fadd_rn(__fmul_rn(x, x), __fmul_rn(y, y)), __fmul_rn(z, z));
    g_pts4[t] = make_float4(x, y, z, nrm);
}

// ---------------- FPS: one block per batch; redux.sync + 2 barriers + smem points ----------------
__global__ __launch_bounds__(1024, 1) void fps_kernel(const float* __restrict__ xyz) {
    extern __shared__ float sm[];
    float* sx = sm;
    float* sy = sm + NN;
    float* sz = sm + 2 * NN;
    u64*   skey  = (u64*)(sm + 3 * NN);
    int*   swidx = (int*)(skey + 32);

    int b = blockIdx.x;
    const float* X = xyz + (size_t)b * 3 * NN;
    int tid = threadIdx.x;
    int lane = tid & 31, wid = tid >> 5;

    // stage point cloud into smem (coalesced)
    for (int i = tid; i < NN; i += 1024) {
        sx[i] = X[i]; sy[i] = X[NN + i]; sz[i] = X[2 * NN + i];
    }

    // register-resident packed coords: pair j holds points (tid+j*1024, tid+(j+4)*1024)
    u64 px2[4], py2[4], pz2[4];
    float ddv[8];
#pragma unroll
    for (int j = 0; j < 4; j++) {
        int plo = tid + j * 1024, phi = tid + (j + 4) * 1024;
        px2[j] = pk2(X[plo], X[phi]);
        py2[j] = pk2(X[NN + plo], X[NN + phi]);
        pz2[j] = pk2(X[2 * NN + plo], X[2 * NN + phi]);
    }
#pragma unroll
    for (int j = 0; j < 8; j++) ddv[j] = 1e10f;

    if (tid == 0) g_fps[b * SS] = 0;
    __syncthreads();

    float cx = sx[0], cy = sy[0], cz = sz[0];

    for (int it = 1; it < SS; it++) {
        u64 ncx = pk2(-cx, -cx), ncy = pk2(-cy, -cy), ncz = pk2(-cz, -cz);
        float n8[8];
#pragma unroll
        for (int j = 0; j < 4; j++) {
            u64 dx = add2(px2[j], ncx);
            u64 dy = add2(py2[j], ncy);
            u64 dz = add2(pz2[j], ncz);
            u64 d2 = add2(add2(mul2(dx, dx), mul2(dy, dy)), mul2(dz, dz));
            float dlo, dhi; upk2(d2, dlo, dhi);
            float a = fminf(ddv[j], dlo);     ddv[j] = a;     n8[j] = a;
            float c = fminf(ddv[j + 4], dhi); ddv[j + 4] = c; n8[j + 4] = c;
        }
        // per-thread argmax, ascending global index (strict > keeps lowest index on ties)
        float bv = -1.0f; int bi = 0x7fffffff;
#pragma unroll
        for (int j = 0; j < 8; j++) {
            if (n8[j] > bv) { bv = n8[j]; bi = tid + j * 1024; }
        }
        // warp argmax via redux (dist >= 0 -> u32-monotonic bits)
        unsigned ub = __float_as_uint(bv);
        unsigned m = __reduce_max_sync(0xffffffffu, ub);
        int cand = (ub == m) ? bi : 0x7fffffff;
        int wbest = __reduce_min_sync(0xffffffffu, cand);
        if (lane == 0) skey[wid] = ((u64)m << 32) | (unsigned)wbest;
        __syncthreads();
        if (wid == 0) {
            u64 kk = skey[lane];
            unsigned hv = (unsigned)(kk >> 32);
            unsigned m2 = __reduce_max_sync(0xffffffffu, hv);
            int c2 = (hv == m2) ? (int)(unsigned)(kk & 0xffffffffu) : 0x7fffffff;
            int w = __reduce_min_sync(0xffffffffu, c2);
            if (lane == 0) { swidx[0] = w; g_fps[b * SS + it] = w; }
        }
        __syncthreads();
        int w = swidx[0];
        cx = sx[w]; cy = sy[w]; cz = sz[w];
    }
}

// ---------------- kNN: warp-distributed sorted top-16 list ----------------
__global__ __launch_bounds__(256) void knn_kernel() {
    __shared__ float4 sp[1024];
    int b = blockIdx.x >> 8;                 // 256 blocks per batch
    int s = ((blockIdx.x & 255) << 3) + (threadIdx.x >> 5);
    int lane = threadIdx.x & 31;

    int qi = g_fps[b * SS + s];
    float4 q = g_pts4[b * NN + qi];

    // lane l holds the rank-l key (ascending); lanes 16..31 are overflow padding
    u64 lst = 0xFFFFFFFFFFFFFFFFull;
    u64 thresh = 0xFFFFFFFFFFFFFFFFull;     // current 16th-best (rank 15)

    for (int ch = 0; ch < 8; ch++) {
        __syncthreads();
#pragma unroll
        for (int i = 0; i < 4; i++)
            sp[threadIdx.x + i * 256] = g_pts4[b * NN + ch * 1024 + threadIdx.x + i * 256];
        __syncthreads();
#pragma unroll 4
        for (int i = 0; i < 32; i++) {
            int ci = lane + i * 32;
            float4 p = sp[ci];
            float dot = q.x * p.x + q.y * p.y + q.z * p.z;
            float d = __fadd_rn(__fadd_rn(__fmul_rn(-2.0f, dot), q.w), p.w);
            int gi = ch * 1024 + ci;
            unsigned u = __float_as_uint(d);
            u ^= (((unsigned)((int)u >> 31)) | 0x80000000u);   // monotonic transform
            u64 key = ((u64)u << 32) | (unsigned)gi;
            unsigned bal = __ballot_sync(0xffffffffu, key < thresh);
            while (bal) {
                int src = __ffs(bal) - 1;
                bal &= bal - 1;
                u64 k = __shfl_sync(0xffffffffu, key, src);
                u64 prev = __shfl_up_sync(0xffffffffu, lst, 1);
                if (lane == 0) prev = 0;
                lst = (lst < k) ? lst : ((prev < k) ? k : prev);
                thresh = __shfl_sync(0xffffffffu, lst, 15);
            }
        }
    }
    if (lane < 16) g_knn[(b * SS + s) * KK + lane] = (int)(unsigned)(lst & 0xffffffffu);
}

// ---------------- conv0: gather(67ch) + GEMM 67->64 + stats ----------------
__global__ __launch_bounds__(128) void conv0_kernel(const float* __restrict__ xyz,
                                                    const float* __restrict__ pts,
                                                    const float* __restrict__ W) {
    extern __shared__ float sm[];
    float* Xs = sm;               // [67][128]
    float* Wt = sm + 67 * 128;    // [67][64] (transposed)
    int tid = threadIdx.x;
    int m0 = blockIdx.x * 128;

    for (int i = tid; i < 67 * 64; i += 128) {
        int o = i / 67, c = i - o * 67;
        Wt[c * 64 + o] = W[i];
    }
    {
        int m = m0 + tid;
        int b = m >> 15; int rem = m & 32767; int s = rem >> 4; int k = rem & 15;
        int ni = g_knn[(((b << 11) + s) << 4) + k];
        int qi = g_fps[(b << 11) + s];
        const float* xb = xyz + (size_t)b * 3 * NN;
        Xs[0 * 128 + tid] = xb[ni] - xb[qi];
        Xs[1 * 128 + tid] = xb[NN + ni] - xb[NN + qi];
        Xs[2 * 128 + tid] = xb[2 * NN + ni] - xb[2 * NN + qi];
        const float* pb = pts + (size_t)b * DD * NN;
#pragma unroll
        for (int c = 0; c < 64; c++) Xs[(c + 3) * 128 + tid] = pb[c * NN + ni];
    }
    __syncthreads();

    int og = tid >> 5, mt = tid & 31;
    float acc[16][4];
#pragma unroll
    for (int o = 0; o < 16; o++)
#pragma unroll
        for (int j = 0; j < 4; j++) acc[o][j] = 0.0f;

    for (int c = 0; c < 67; c++) {
        float4 xv = *(const float4*)(Xs + c * 128 + mt * 4);
        float w[16];
        *(float4*)&w[0]  = *(const float4*)(Wt + c * 64 + og * 16);
        *(float4*)&w[4]  = *(const float4*)(Wt + c * 64 + og * 16 + 4);
        *(float4*)&w[8]  = *(const float4*)(Wt + c * 64 + og * 16 + 8);
        *(float4*)&w[12] = *(const float4*)(Wt + c * 64 + og * 16 + 12);
#pragma unroll
        for (int o = 0; o < 16; o++) {
            acc[o][0] += w[o] * xv.x; acc[o][1] += w[o] * xv.y;
            acc[o][2] += w[o] * xv.z; acc[o][3] += w[o] * xv.w;
        }
    }
    float s1[16], s2[16];
#pragma unroll
    for (int o = 0; o < 16; o++) {
        float4 v = make_float4(acc[o][0], acc[o][1], acc[o][2], acc[o][3]);
        *(float4*)(g_y0 + (size_t)(og * 16 + o) * MTOT + m0 + mt * 4) = v;
        s1[o] = v.x + v.y + v.z + v.w;
        s2[o] = v.x * v.x + v.y * v.y + v.z * v.z + v.w * v.w;
    }
#pragma unroll
    for (int off = 16; off; off >>= 1) {
#pragma unroll
        for (int o = 0; o < 16; o++) {
            s1[o] += __shfl_down_sync(0xffffffffu, s1[o], off);
            s2[o] += __shfl_down_sync(0xffffffffu, s2[o], off);
        }
    }
    if (mt == 0) {
#pragma unroll
        for (int o = 0; o < 16; o++) {
            atomicAdd(&g_raw[og * 16 + o], s1[o]);
            atomicAdd(&g_raw[64 + og * 16 + o], s2[o]);
        }
    }
}

// ---------------- mid conv: apply prev BN+leaky, GEMM, stats ----------------
template <int CIN, int COUT>
__global__ __launch_bounds__((COUT / 16) * 32) void convmid_kernel(
    const float* __restrict__ Yin, float* __restrict__ Yout,
    const float* __restrict__ W, int stIn, int rawOut) {
    constexpr int TPB = (COUT / 16) * 32;
    extern __shared__ float sm[];
    float* Xs = sm;                 // [CIN][128]
    float* Wt = sm + CIN * 128;     // [CIN][COUT]
    int tid = threadIdx.x;
    int m0 = blockIdx.x * 128;

    for (int i = tid; i < CIN * COUT; i += TPB) {
        int o = i / CIN, c = i - o * CIN;
        Wt[c * COUT + o] = W[i];
    }
    for (int i = tid; i < CIN * 128; i += TPB) {
        int c = i >> 7, ml = i & 127;
        float v = Yin[(size_t)c * MTOT + m0 + ml];
        v = v * g_st[stIn + c] + g_st[stIn + CIN + c];
        v = (v > 0.0f) ? v : 0.1f * v;
        Xs[i] = v;
    }
    __syncthreads();

    int og = tid >> 5, mt = tid & 31;
    float acc[16][4];
#pragma unroll
    for (int o = 0; o < 16; o++)
#pragma unroll
        for (int j = 0; j < 4; j++) acc[o][j] = 0.0f;

    for (int c = 0; c < CIN; c++) {
        float4 xv = *(const float4*)(Xs + c * 128 + mt * 4);
        float w[16];
        *(float4*)&w[0]  = *(const float4*)(Wt + c * COUT + og * 16);
        *(float4*)&w[4]  = *(const float4*)(Wt + c * COUT + og * 16 + 4);
        *(float4*)&w[8]  = *(const float4*)(Wt + c * COUT + og * 16 + 8);
        *(float4*)&w[12] = *(const float4*)(Wt + c * COUT + og * 16 + 12);
#pragma unroll
        for (int o = 0; o < 16; o++) {
            acc[o][0] += w[o] * xv.x; acc[o][1] += w[o] * xv.y;
            acc[o][2] += w[o] * xv.z; acc[o][3] += w[o] * xv.w;
        }
    }
    float s1[16], s2[16];
#pragma unroll
    for (int o = 0; o < 16; o++) {
        float4 v = make_float4(acc[o][0], acc[o][1], acc[o][2], acc[o][3]);
        *(float4*)(Yout + (size_t)(og * 16 + o) * MTOT + m0 + mt * 4) = v;
        s1[o] = v.x + v.y + v.z + v.w;
        s2[o] = v.x * v.x + v.y * v.y + v.z * v.z + v.w * v.w;
    }
#pragma unroll
    for (int off = 16; off; off >>= 1) {
#pragma unroll
        for (int o = 0; o < 16; o++) {
            s1[o] += __shfl_down_sync(0xffffffffu, s1[o], off);
            s2[o] += __shfl_down_sync(0xffffffffu, s2[o], off);
        }
    }
    if (mt == 0) {
#pragma unroll
        for (int o = 0; o < 16; o++) {
            atomicAdd(&g_raw[rawOut + og * 16 + o], s1[o]);
            atomicAdd(&g_raw[rawOut + COUT + og * 16 + o], s2[o]);
        }
    }
}

// ---------------- finalize BN stats -> folded scale/shift ----------------
__global__ void finalize_kernel(int rawOff, int stOff, int C,
                                const float* __restrict__ gamma,
                                const float* __restrict__ beta) {
    int c = threadIdx.x;
    if (c < C) {
        float su = g_raw[rawOff + c], sq = g_raw[rawOff + C + c];
        float mean = su * NEL_INV;
        float var = sq * NEL_INV - mean * mean;
        float s = gamma[c] * rsqrtf(var + 1e-5f);
        g_st[stOff + c] = s;
        g_st[stOff + C + c] = beta[c] - mean * s;
    }
}

// ---------------- final: bn2 + leaky + max over K -> feat ----------------
__global__ __launch_bounds__(256) void feat_kernel(float* __restrict__ out) {
    int t = blockIdx.x * 256 + threadIdx.x;   // 1,048,576 = B*128*S
    int s = t & 2047;
    int o = (t >> 11) & 127;
    int b = t >> 18;
    float sc = g_st[256 + o], tb = g_st[384 + o];
    const float4* yp = (const float4*)(g_y2 + (size_t)o * MTOT + (size_t)(((b << 11) + s) << 4));
    float mx = -f_inf();
#pragma unroll
    for (int i = 0; i < 4; i++) {
        float4 v = yp[i];
        float a;
        a = v.x * sc + tb; a = (a > 0.0f) ? a : 0.1f * a; mx = fmaxf(mx, a);
        a = v.y * sc + tb; a = (a > 0.0f) ? a : 0.1f * a; mx = fmaxf(mx, a);
        a = v.z * sc + tb; a = (a > 0.0f) ? a : 0.1f * a; mx = fmaxf(mx, a);
        a = v.w * sc + tb; a = (a > 0.0f) ? a : 0.1f * a; mx = fmaxf(mx, a);
    }
    out[24576 + (size_t)(((b << 7) | o) << 11) + s] = mx;
}

// ---------------- aux: new_xyz + fps_idx ----------------
__global__ __launch_bounds__(256) void aux_kernel(const float* __restrict__ xyz,
                                                  float* __restrict__ out) {
    int t = blockIdx.x * 256 + threadIdx.x;   // 32768 = B*4*S
    int b = t >> 13;
    int r = t & 8191;
    int c = r >> 11;       // 0..3
    int s = r & 2047;
    int fi = g_fps[(b << 11) + s];
    if (c < 3) out[(size_t)(((b * 3 + c) << 11)) + s] = xyz[(size_t)(b * 3 + c) * NN + fi];
    else       out[24576 + 1048576 + (size_t)(b << 11) + s] = (float)fi;
}

// ---------------- launch ----------------
extern "C" void kernel_launch(void* const* d_in, const int* in_sizes, int n_in,
                              void* d_out, int out_size) {
    const float* xyz = (const float*)d_in[0];
    const float* pts = (const float*)d_in[1];
    const float* w0  = (const float*)d_in[2];
    const float* w1  = (const float*)d_in[3];
    const float* w2  = (const float*)d_in[4];
    const float* bn0g = (const float*)d_in[5];
    const float* bn0b = (const float*)d_in[6];
    const float* bn1g = (const float*)d_in[7];
    const float* bn1b = (const float*)d_in[8];
    const float* bn2g = (const float*)d_in[9];
    const float* bn2b = (const float*)d_in[10];
    float* out = (float*)d_out;

    float *y0p, *y1p, *y2p;
    cudaGetSymbolAddress((void**)&y0p, g_y0);
    cudaGetSymbolAddress((void**)&y1p, g_y1);
    cudaGetSymbolAddress((void**)&y2p, g_y2);

    const int SMF = 3 * NN * 4 + 32 * 8 + 16;     // fps: points + warp keys + winner
    const int SM0 = (67 * 128 + 67 * 64) * 4;     // 51456
    const int SM1 = (64 * 128 + 64 * 64) * 4;     // 49152
    const int SM2 = (64 * 128 + 64 * 128) * 4;    // 65536
    cudaFuncSetAttribute(fps_kernel, cudaFuncAttributeMaxDynamicSharedMemorySize, SMF);
    cudaFuncSetAttribute(conv0_kernel, cudaFuncAttributeMaxDynamicSharedMemorySize, SM0);
    cudaFuncSetAttribute(convmid_kernel<64, 64>, cudaFuncAttributeMaxDynamicSharedMemorySize, SM1);
    cudaFuncSetAttribute(convmid_kernel<64, 128>, cudaFuncAttributeMaxDynamicSharedMemorySize, SM2);

    zero_kernel<<<1, 512>>>();
    prep_kernel<<<(BB * NN) / 256, 256>>>(xyz);
    fps_kernel<<<BB, 1024, SMF>>>(xyz);
    knn_kernel<<<1024, 256>>>();
    conv0_kernel<<<MTOT / 128, 128, SM0>>>(xyz, pts, w0);
    finalize_kernel<<<1, 64>>>(0, 0, 64, bn0g, bn0b);
    convmid_kernel<64, 64><<<MTOT / 128, 128, SM1>>>(y0p, y1p, w1, 0, 128);
    finalize_kernel<<<1, 64>>>(128, 128, 64, bn1g, bn1b);
    convmid_kernel<64, 128><<<MTOT / 128, 256, SM2>>>(y1p, y2p, w2, 128, 256);
    finalize_kernel<<<1, 128>>>(256, 256, 128, bn2g, bn2b);
    feat_kernel<<<(BB * 128 * SS) / 256, 256>>>(out);
    aux_kernel<<<(BB * 4 * SS) / 256, 256>>>(xyz, out);
}

// round 4
// speedup vs baseline: 2.3315x; 1.0177x over previous
#include <cuda_runtime.h>
#include <cuda_bf16.h>
#include <cstdint>

#define BB 4
#define NN 8192
#define SS 2048
#define KK 16
#define DD 64
#define MTOT (BB*SS*KK)   // 131072
#define NEL_INV (1.0f/131072.0f)

typedef unsigned long long u64;

// ---------------- scratch (__device__ globals; no runtime alloc) ----------------
__device__ float4 g_pts4[BB*NN];          // x,y,z,|p|^2
__device__ float  g_ptsT[BB*NN*DD];       // points transposed: [b*NN+n][64]
__device__ int    g_fps [BB*SS];
__device__ int    g_knn [BB*SS*KK];
__device__ float  g_y0  [64 * MTOT];
__device__ float  g_y1  [64 * MTOT];
__device__ float  g_y2  [128 * MTOT];
__device__ float  g_raw [512];            // sum/sumsq per layer
__device__ float  g_st  [512];            // folded scale/shift per layer

__device__ __forceinline__ float f_inf() { return __int_as_float(0x7f800000); }

// packed f32x2 helpers (element-wise .rn — bit-identical to scalar __fmul_rn/__fadd_rn)
__device__ __forceinline__ u64 pk2(float lo, float hi) {
    u64 r; asm("mov.b64 %0,{%1,%2};" : "=l"(r) : "f"(lo), "f"(hi)); return r;
}
__device__ __forceinline__ void upk2(u64 v, float& lo, float& hi) {
    asm("mov.b64 {%0,%1},%2;" : "=f"(lo), "=f"(hi) : "l"(v));
}
__device__ __forceinline__ u64 add2(u64 a, u64 b) {
    u64 r; asm("add.rn.f32x2 %0,%1,%2;" : "=l"(r) : "l"(a), "l"(b)); return r;
}
__device__ __forceinline__ u64 mul2(u64 a, u64 b) {
    u64 r; asm("mul.rn.f32x2 %0,%1,%2;" : "=l"(r) : "l"(a), "l"(b)); return r;
}

// ---------------- zero stats ----------------
__global__ void zero_kernel() { g_raw[threadIdx.x] = 0.0f; }

// ---------------- pack points + norms ----------------
__global__ void prep_kernel(const float* __restrict__ xyz) {
    int t = blockIdx.x * 256 + threadIdx.x;      // 0..32767
    int b = t >> 13, n = t & (NN - 1);
    const float* X = xyz + (size_t)b * 3 * NN;
    float x = X[n], y = X[NN + n], z = X[2 * NN + n];
    float nrm = __fadd_rn(__fadd_rn(__fmul_rn(x, x), __fmul_rn(y, y)), __fmul_rn(z, z));
    g_pts4[t] = make_float4(x, y, z, nrm);
}

// ---------------- transpose points [D][N] -> [N][D] ----------------
__global__ __launch_bounds__(256) void transpose_kernel(const float* __restrict__ pts) {
    __shared__ float tile[32 * 65];
    int b = blockIdx.x >> 8;              // 256 blocks per batch
    int n0 = (blockIdx.x & 255) << 5;     // 32 points per block
    const float* pb = pts + (size_t)b * DD * NN;
    int tid = threadIdx.x;
#pragma unroll
    for (int i = tid; i < 64 * 32; i += 256) {
        int c = i >> 5, n = i & 31;
        tile[n * 65 + c] = pb[c * NN + n0 + n];
    }
    __syncthreads();
#pragma unroll
    for (int i = tid; i < 64 * 32; i += 256) {
        int n = i >> 6, c = i & 63;
        g_ptsT[(((size_t)(b << 13) + n0 + n) << 6) + c] = tile[n * 65 + c];
    }
}

// ---------------- FPS: one block/batch; 1 barrier/iter, all-warp stage2 ----------------
__global__ __launch_bounds__(1024, 1) void fps_kernel(const float* __restrict__ xyz) {
    extern __shared__ float sm[];
    float*    sx = sm;
    float*    sy = sm + NN;
    float*    sz = sm + 2 * NN;
    unsigned* svv = (unsigned*)(sm + 3 * NN);   // [2][32] warp max bits
    int*      sii = (int*)(svv + 64);           // [2][32] warp argmax idx

    int b = blockIdx.x;
    const float* X = xyz + (size_t)b * 3 * NN;
    int tid = threadIdx.x;
    int lane = tid & 31;

    // stage point cloud into smem (coalesced)
    for (int i = tid; i < NN; i += 1024) {
        sx[i] = X[i]; sy[i] = X[NN + i]; sz[i] = X[2 * NN + i];
    }

    // register-resident packed coords: pair j holds points (tid+j*1024, tid+(j+4)*1024)
    u64 px2[4], py2[4], pz2[4];
    float ddv[8];
#pragma unroll
    for (int j = 0; j < 4; j++) {
        int plo = tid + j * 1024, phi = tid + (j + 4) * 1024;
        px2[j] = pk2(X[plo], X[phi]);
        py2[j] = pk2(X[NN + plo], X[NN + phi]);
        pz2[j] = pk2(X[2 * NN + plo], X[2 * NN + phi]);
    }
#pragma unroll
    for (int j = 0; j < 8; j++) ddv[j] = 1e10f;

    if (tid == 0) g_fps[b * SS] = 0;
    float cx = X[0], cy = X[NN], cz = X[2 * NN];
    __syncthreads();

    for (int it = 1; it < SS; it++) {
        u64 ncx = pk2(-cx, -cx), ncy = pk2(-cy, -cy), ncz = pk2(-cz, -cz);
        float n8[8];
#pragma unroll
        for (int j = 0; j < 4; j++) {
            u64 dx = add2(px2[j], ncx);
            u64 dy = add2(py2[j], ncy);
            u64 dz = add2(pz2[j], ncz);
            u64 d2 = add2(add2(mul2(dx, dx), mul2(dy, dy)), mul2(dz, dz));
            float dlo, dhi; upk2(d2, dlo, dhi);
            float a = fminf(ddv[j], dlo);     ddv[j] = a;     n8[j] = a;
            float c = fminf(ddv[j + 4], dhi); ddv[j + 4] = c; n8[j + 4] = c;
        }
        // per-thread max (values >= 0 -> u32-monotonic bits)
        float m01 = fmaxf(n8[0], n8[1]), m23 = fmaxf(n8[2], n8[3]);
        float m45 = fmaxf(n8[4], n8[5]), m67 = fmaxf(n8[6], n8[7]);
        float bv = fmaxf(fmaxf(m01, m23), fmaxf(m45, m67));
        unsigned ub = __float_as_uint(bv);
        unsigned m = __reduce_max_sync(0xffffffffu, ub);
        int bi = 0x7fffffff;
        if (ub == m) {
#pragma unroll
            for (int j = 7; j >= 0; j--)
                if (__float_as_uint(n8[j]) == m) bi = tid + j * 1024;
        }
        int wbest = __reduce_min_sync(0xffffffffu, bi);
        int p = (it & 1) << 5;
        if (lane == 0) { svv[p + (tid >> 5)] = m; sii[p + (tid >> 5)] = wbest; }
        __syncthreads();
        // every warp reduces all 32 warp keys (no 2nd barrier, no broadcast)
        unsigned hv = svv[p + lane];
        unsigned m2 = __reduce_max_sync(0xffffffffu, hv);
        int c2 = (hv == m2) ? sii[p + lane] : 0x7fffffff;
        int w = __reduce_min_sync(0xffffffffu, c2);
        if (tid == 0) g_fps[b * SS + it] = w;
        cx = sx[w]; cy = sy[w]; cz = sz[w];
    }
}

// ---------------- kNN: warp-distributed sorted top-16 list ----------------
__global__ __launch_bounds__(256) void knn_kernel() {
    __shared__ float4 sp[1024];
    int b = blockIdx.x >> 8;                 // 256 blocks per batch
    int s = ((blockIdx.x & 255) << 3) + (threadIdx.x >> 5);
    int lane = threadIdx.x & 31;

    int qi = g_fps[b * SS + s];
    float4 q = g_pts4[b * NN + qi];

    // lane l holds the rank-l key (ascending); lanes 16..31 are overflow padding
    u64 lst = 0xFFFFFFFFFFFFFFFFull;
    u64 thresh = 0xFFFFFFFFFFFFFFFFull;     // current 16th-best (rank 15)

    for (int ch = 0; ch < 8; ch++) {
        __syncthreads();
#pragma unroll
        for (int i = 0; i < 4; i++)
            sp[threadIdx.x + i * 256] = g_pts4[b * NN + ch * 1024 + threadIdx.x + i * 256];
        __syncthreads();
#pragma unroll 4
        for (int i = 0; i < 32; i++) {
            int ci = lane + i * 32;
            float4 p = sp[ci];
            float dot = q.x * p.x + q.y * p.y + q.z * p.z;
            float d = __fadd_rn(__fadd_rn(__fmul_rn(-2.0f, dot), q.w), p.w);
            int gi = ch * 1024 + ci;
            unsigned u = __float_as_uint(d);
            u ^= (((unsigned)((int)u >> 31)) | 0x80000000u);   // monotonic transform
            u64 key = ((u64)u << 32) | (unsigned)gi;
            unsigned bal = __ballot_sync(0xffffffffu, key < thresh);
            while (bal) {
                int src = __ffs(bal) - 1;
                bal &= bal - 1;
                u64 k = __shfl_sync(0xffffffffu, key, src);
                u64 prev = __shfl_up_sync(0xffffffffu, lst, 1);
                if (lane == 0) prev = 0;
                lst = (lst < k) ? lst : ((prev < k) ? k : prev);
                thresh = __shfl_sync(0xffffffffu, lst, 15);
            }
        }
    }
    if (lane < 16) g_knn[(b * SS + s) * KK + lane] = (int)(unsigned)(lst & 0xffffffffu);
}

// ---------------- conv0: gather(67ch) + GEMM 67->64 + stats ----------------
__global__ __launch_bounds__(128) void conv0_kernel(const float* __restrict__ W) {
    extern __shared__ float sm[];
    float* Xs = sm;               // [67][128]
    float* Wt = sm + 67 * 128;    // [67][64] (transposed)
    int tid = threadIdx.x;
    int m0 = blockIdx.x * 128;

    for (int i = tid; i < 67 * 64; i += 128) {
        int o = i / 67, c = i - o * 67;
        Wt[c * 64 + o] = W[i];
    }
    {
        int m = m0 + tid;
        int b = m >> 15; int rem = m & 32767; int s = rem >> 4; int k = rem & 15;
        int ni = g_knn[(((b << 11) + s) << 4) + k];
        int qi = g_fps[(b << 11) + s];
        float4 pn = g_pts4[(b << 13) + ni];
        float4 pq = g_pts4[(b << 13) + qi];
        Xs[0 * 128 + tid] = __fsub_rn(pn.x, pq.x);
        Xs[1 * 128 + tid] = __fsub_rn(pn.y, pq.y);
        Xs[2 * 128 + tid] = __fsub_rn(pn.z, pq.z);
        const float4* prow = (const float4*)(g_ptsT + (((size_t)(b << 13) + ni) << 6));
#pragma unroll
        for (int c4 = 0; c4 < 16; c4++) {
            float4 v = prow[c4];
            Xs[(3 + c4 * 4 + 0) * 128 + tid] = v.x;
            Xs[(3 + c4 * 4 + 1) * 128 + tid] = v.y;
            Xs[(3 + c4 * 4 + 2) * 128 + tid] = v.z;
            Xs[(3 + c4 * 4 + 3) * 128 + tid] = v.w;
        }
    }
    __syncthreads();

    int og = tid >> 5, mt = tid & 31;
    float acc[16][4];
#pragma unroll
    for (int o = 0; o < 16; o++)
#pragma unroll
        for (int j = 0; j < 4; j++) acc[o][j] = 0.0f;

    for (int c = 0; c < 67; c++) {
        float4 xv = *(const float4*)(Xs + c * 128 + mt * 4);
        float w[16];
        *(float4*)&w[0]  = *(const float4*)(Wt + c * 64 + og * 16);
        *(float4*)&w[4]  = *(const float4*)(Wt + c * 64 + og * 16 + 4);
        *(float4*)&w[8]  = *(const float4*)(Wt + c * 64 + og * 16 + 8);
        *(float4*)&w[12] = *(const float4*)(Wt + c * 64 + og * 16 + 12);
#pragma unroll
        for (int o = 0; o < 16; o++) {
            acc[o][0] += w[o] * xv.x; acc[o][1] += w[o] * xv.y;
            acc[o][2] += w[o] * xv.z; acc[o][3] += w[o] * xv.w;
        }
    }
    float s1[16], s2[16];
#pragma unroll
    for (int o = 0; o < 16; o++) {
        float4 v = make_float4(acc[o][0], acc[o][1], acc[o][2], acc[o][3]);
        *(float4*)(g_y0 + (size_t)(og * 16 + o) * MTOT + m0 + mt * 4) = v;
        s1[o] = v.x + v.y + v.z + v.w;
        s2[o] = v.x * v.x + v.y * v.y + v.z * v.z + v.w * v.w;
    }
#pragma unroll
    for (int off = 16; off; off >>= 1) {
#pragma unroll
        for (int o = 0; o < 16; o++) {
            s1[o] += __shfl_down_sync(0xffffffffu, s1[o], off);
            s2[o] += __shfl_down_sync(0xffffffffu, s2[o], off);
        }
    }
    if (mt == 0) {
#pragma unroll
        for (int o = 0; o < 16; o++) {
            atomicAdd(&g_raw[og * 16 + o], s1[o]);
            atomicAdd(&g_raw[64 + og * 16 + o], s2[o]);
        }
    }
}

// ---------------- mid conv: apply prev BN+leaky, GEMM, stats ----------------
template <int CIN, int COUT>
__global__ __launch_bounds__((COUT / 16) * 32) void convmid_kernel(
    const float* __restrict__ Yin, float* __restrict__ Yout,
    const float* __restrict__ W, int stIn, int rawOut) {
    constexpr int TPB = (COUT / 16) * 32;
    extern __shared__ float sm[];
    float* Xs = sm;                 // [CIN][128]
    float* Wt = sm + CIN * 128;     // [CIN][COUT]
    int tid = threadIdx.x;
    int m0 = blockIdx.x * 128;

    for (int i = tid; i < CIN * COUT; i += TPB) {
        int o = i / CIN, c = i - o * CIN;
        Wt[c * COUT + o] = W[i];
    }
    for (int i = tid; i < CIN * 32; i += TPB) {
        int c = i >> 5, ml4 = i & 31;
        float4 v = *(const float4*)(Yin + (size_t)c * MTOT + m0 + ml4 * 4);
        float sc = g_st[stIn + c], sh = g_st[stIn + CIN + c];
        v.x = v.x * sc + sh; v.x = (v.x > 0.0f) ? v.x : 0.1f * v.x;
        v.y = v.y * sc + sh; v.y = (v.y > 0.0f) ? v.y : 0.1f * v.y;
        v.z = v.z * sc + sh; v.z = (v.z > 0.0f) ? v.z : 0.1f * v.z;
        v.w = v.w * sc + sh; v.w = (v.w > 0.0f) ? v.w : 0.1f * v.w;
        *(float4*)(Xs + c * 128 + ml4 * 4) = v;
    }
    __syncthreads();

    int og = tid >> 5, mt = tid & 31;
    float acc[16][4];
#pragma unroll
    for (int o = 0; o < 16; o++)
#pragma unroll
        for (int j = 0; j < 4; j++) acc[o][j] = 0.0f;

    for (int c = 0; c < CIN; c++) {
        float4 xv = *(const float4*)(Xs + c * 128 + mt * 4);
        float w[16];
        *(float4*)&w[0]  = *(const float4*)(Wt + c * COUT + og * 16);
        *(float4*)&w[4]  = *(const float4*)(Wt + c * COUT + og * 16 + 4);
        *(float4*)&w[8]  = *(const float4*)(Wt + c * COUT + og * 16 + 8);
        *(float4*)&w[12] = *(const float4*)(Wt + c * COUT + og * 16 + 12);
#pragma unroll
        for (int o = 0; o < 16; o++) {
            acc[o][0] += w[o] * xv.x; acc[o][1] += w[o] * xv.y;
            acc[o][2] += w[o] * xv.z; acc[o][3] += w[o] * xv.w;
        }
    }
    float s1[16], s2[16];
#pragma unroll
    for (int o = 0; o < 16; o++) {
        float4 v = make_float4(acc[o][0], acc[o][1], acc[o][2], acc[o][3]);
        *(float4*)(Yout + (size_t)(og * 16 + o) * MTOT + m0 + mt * 4) = v;
        s1[o] = v.x + v.y + v.z + v.w;
        s2[o] = v.x * v.x + v.y * v.y + v.z * v.z + v.w * v.w;
    }
#pragma unroll
    for (int off = 16; off; off >>= 1) {
#pragma unroll
        for (int o = 0; o < 16; o++) {
            s1[o] += __shfl_down_sync(0xffffffffu, s1[o], off);
            s2[o] += __shfl_down_sync(0xffffffffu, s2[o], off);
        }
    }
    if (mt == 0) {
#pragma unroll
        for (int o = 0; o < 16; o++) {
            atomicAdd(&g_raw[rawOut + og * 16 + o], s1[o]);
            atomicAdd(&g_raw[rawOut + COUT + og * 16 + o], s2[o]);
        }
    }
}

// ---------------- finalize BN stats -> folded scale/shift ----------------
__global__ void finalize_kernel(int rawOff, int stOff, int C,
                                const float* __restrict__ gamma,
                                const float* __restrict__ beta) {
    int c = threadIdx.x;
    if (c < C) {
        float su = g_raw[rawOff + c], sq = g_raw[rawOff + C + c];
        float mean = su * NEL_INV;
        float var = sq * NEL_INV - mean * mean;
        float s = gamma[c] * rsqrtf(var + 1e-5f);
        g_st[stOff + c] = s;
        g_st[stOff + C + c] = beta[c] - mean * s;
    }
}

// ---------------- final: bn2 + leaky + max over K -> feat ----------------
__global__ __launch_bounds__(256) void feat_kernel(float* __restrict__ out) {
    int t = blockIdx.x * 256 + threadIdx.x;   // 1,048,576 = B*128*S
    int s = t & 2047;
    int o = (t >> 11) & 127;
    int b = t >> 18;
    float sc = g_st[256 + o], tb = g_st[384 + o];
    const float4* yp = (const float4*)(g_y2 + (size_t)o * MTOT + (size_t)(((b << 11) + s) << 4));
    float mx = -f_inf();
#pragma unroll
    for (int i = 0; i < 4; i++) {
        float4 v = yp[i];
        float a;
        a = v.x * sc + tb; a = (a > 0.0f) ? a : 0.1f * a; mx = fmaxf(mx, a);
        a = v.y * sc + tb; a = (a > 0.0f) ? a : 0.1f * a; mx = fmaxf(mx, a);
        a = v.z * sc + tb; a = (a > 0.0f) ? a : 0.1f * a; mx = fmaxf(mx, a);
        a = v.w * sc + tb; a = (a > 0.0f) ? a : 0.1f * a; mx = fmaxf(mx, a);
    }
    out[24576 + (size_t)(((b << 7) | o) << 11) + s] = mx;
}

// ---------------- aux: new_xyz + fps_idx ----------------
__global__ __launch_bounds__(256) void aux_kernel(const float* __restrict__ xyz,
                                                  float* __restrict__ out) {
    int t = blockIdx.x * 256 + threadIdx.x;   // 32768 = B*4*S
    int b = t >> 13;
    int r = t & 8191;
    int c = r >> 11;       // 0..3
    int s = r & 2047;
    int fi = g_fps[(b << 11) + s];
    if (c < 3) out[(size_t)(((b * 3 + c) << 11)) + s] = xyz[(size_t)(b * 3 + c) * NN + fi];
    else       out[24576 + 1048576 + (size_t)(b << 11) + s] = (float)fi;
}

// ---------------- launch ----------------
extern "C" void kernel_launch(void* const* d_in, const int* in_sizes, int n_in,
                              void* d_out, int out_size) {
    const float* xyz = (const float*)d_in[0];
    const float* pts = (const float*)d_in[1];
    const float* w0  = (const float*)d_in[2];
    const float* w1  = (const float*)d_in[3];
    const float* w2  = (const float*)d_in[4];
    const float* bn0g = (const float*)d_in[5];
    const float* bn0b = (const float*)d_in[6];
    const float* bn1g = (const float*)d_in[7];
    const float* bn1b = (const float*)d_in[8];
    const float* bn2g = (const float*)d_in[9];
    const float* bn2b = (const float*)d_in[10];
    float* out = (float*)d_out;

    float *y0p, *y1p, *y2p;
    cudaGetSymbolAddress((void**)&y0p, g_y0);
    cudaGetSymbolAddress((void**)&y1p, g_y1);
    cudaGetSymbolAddress((void**)&y2p, g_y2);

    const int SMF = 3 * NN * 4 + 64 * 4 + 64 * 4;  // fps: points + 2x32 keys (uint+int)
    const int SM0 = (67 * 128 + 67 * 64) * 4;      // 51456
    const int SM1 = (64 * 128 + 64 * 64) * 4;      // 49152
    const int SM2 = (64 * 128 + 64 * 128) * 4;     // 65536
    cudaFuncSetAttribute(fps_kernel, cudaFuncAttributeMaxDynamicSharedMemorySize, SMF);
    cudaFuncSetAttribute(conv0_kernel, cudaFuncAttributeMaxDynamicSharedMemorySize, SM0);
    cudaFuncSetAttribute(convmid_kernel<64, 64>, cudaFuncAttributeMaxDynamicSharedMemorySize, SM1);
    cudaFuncSetAttribute(convmid_kernel<64, 128>, cudaFuncAttributeMaxDynamicSharedMemorySize, SM2);

    zero_kernel<<<1, 512>>>();
    prep_kernel<<<(BB * NN) / 256, 256>>>(xyz);
    transpose_kernel<<<1024, 256>>>(pts);
    fps_kernel<<<BB, 1024, SMF>>>(xyz);
    knn_kernel<<<1024, 256>>>();
    conv0_kernel<<<MTOT / 128, 128, SM0>>>(w0);
    finalize_kernel<<<1, 64>>>(0, 0, 64, bn0g, bn0b);
    convmid_kernel<64, 64><<<MTOT / 128, 128, SM1>>>(y0p, y1p, w1, 0, 128);
    finalize_kernel<<<1, 64>>>(128, 128, 64, bn1g, bn1b);
    convmid_kernel<64, 128><<<MTOT / 128, 256, SM2>>>(y1p, y2p, w2, 128, 256);
    finalize_kernel<<<1, 128>>>(256, 256, 128, bn2g, bn2b);
    feat_kernel<<<(BB * 128 * SS) / 256, 256>>>(out);
    aux_kernel<<<(BB * 4 * SS) / 256, 256>>>(xyz, out);
}